// round 2
// baseline (speedup 1.0000x reference)
#include <cuda_runtime.h>
#include <mma.h>
#include <math.h>
#include <stdint.h>

using namespace nvcuda;

#define BB   2
#define SS   8192
#define DD   1024
#define NWIN 7
#define NBW  14
#define WLEN 2048
#define GG   128

// ---------------- static scratch ----------------
__device__ float g_Sscr [(size_t)NBW * WLEN * WLEN];   // scores; reused as mw logits
__device__ float g_Oscr [(size_t)NBW * WLEN * DD];     // window outs; reused as mixed
__device__ float g_local[(size_t)BB * SS * DD];
__device__ float g_glob [(size_t)BB * SS * DD];
__device__ float g_xt   [(size_t)BB * DD * SS];
__device__ float g_bcast[(size_t)BB * SS * DD];
__device__ float g_gt   [(size_t)BB * 256 * DD];
__device__ float g_lg2  [(size_t)BB * SS * 256];
__device__ float g_Wc2  [(size_t)DD * 4096];

struct GP {
    const float* A; const float* B; float* C;
    int lda, ldb, ldc;
    long sA, sB, sC;
    int K;
    float alpha;
    int beta;
    int winA, winB;
    int causal;
    int klimit;
};

__device__ __forceinline__ long window_off(int z) {
    return (long)(z / NWIN) * ((long)SS * DD) + (long)(z % NWIN) * (1024L * DD);
}

template<int TB>   // TB=1: C = A*B^T ; TB=0: C = A*B   (A,B row-major)
__global__ void __launch_bounds__(256) gemm_tf32(GP p) {
    constexpr int BM = 128, BN = 128, BK = 16, BKP = 20, BNP = 132;
    int i0 = blockIdx.y * BM;
    int j0 = blockIdx.x * BN;
    if (p.causal && j0 > i0) return;
    int z = blockIdx.z;
    const float* A  = p.A + (p.winA ? window_off(z) : z * p.sA);
    const float* Bm = p.B + (p.winB ? window_off(z) : z * p.sB);
    float* C = p.C + z * p.sC;
    int K  = p.klimit ? min(p.K, i0 + BM) : p.K;
    int KT = K / BK;

    __shared__ __align__(32) float As[2][BM][BKP];
    constexpr int BRW = TB ? BN : BK;
    constexpr int BCL = TB ? BKP : BNP;
    __shared__ __align__(32) float Bs[2][BRW][BCL];

    int tid = threadIdx.x;
    int ar = tid >> 2, ac = (tid & 3) << 2;
    int br, bcd;
    if (TB) { br = tid >> 2;  bcd = (tid & 3) << 2;  }
    else    { br = tid >> 5;  bcd = (tid & 31) << 2; }

    const float* Ald0 = A + (long)(i0 + ar) * p.lda + ac;
    const float* Bld0 = TB ? (Bm + (long)(j0 + br) * p.ldb + bcd)
                           : (Bm + (long)br * p.ldb + j0 + bcd);

    float4 pa0, pa1, pb0, pb1;
    pa0 = *(const float4*)(Ald0);
    pa1 = *(const float4*)(Ald0 + (long)64 * p.lda);
    if (TB) { pb0 = *(const float4*)(Bld0); pb1 = *(const float4*)(Bld0 + (long)64 * p.ldb); }
    else    { pb0 = *(const float4*)(Bld0); pb1 = *(const float4*)(Bld0 + (long)8  * p.ldb); }
    *(float4*)&As[0][ar][ac]      = pa0;
    *(float4*)&As[0][ar + 64][ac] = pa1;
    if (TB) { *(float4*)&Bs[0][br][bcd] = pb0; *(float4*)&Bs[0][br + 64][bcd] = pb1; }
    else    { *(float4*)&Bs[0][br][bcd] = pb0; *(float4*)&Bs[0][br + 8][bcd]  = pb1; }
    __syncthreads();

    int wid = tid >> 5;
    int wr  = (wid & 3) * 32;
    int wc  = (wid >> 2) * 64;

    wmma::fragment<wmma::accumulator, 16, 16, 8, float> acc[2][4];
    #pragma unroll
    for (int i = 0; i < 2; i++)
        #pragma unroll
        for (int j = 0; j < 4; j++) wmma::fill_fragment(acc[i][j], 0.0f);

    for (int kt = 0; kt < KT; kt++) {
        int cur = kt & 1;
        bool more = (kt + 1 < KT);
        if (more) {
            const float* Aq = Ald0 + (kt + 1) * BK;
            pa0 = *(const float4*)Aq;
            pa1 = *(const float4*)(Aq + (long)64 * p.lda);
            if (TB) {
                const float* Bq = Bld0 + (kt + 1) * BK;
                pb0 = *(const float4*)Bq; pb1 = *(const float4*)(Bq + (long)64 * p.ldb);
            } else {
                const float* Bq = Bld0 + (long)(kt + 1) * BK * p.ldb;
                pb0 = *(const float4*)Bq; pb1 = *(const float4*)(Bq + (long)8 * p.ldb);
            }
        }
        #pragma unroll
        for (int ks = 0; ks < 2; ks++) {
            wmma::fragment<wmma::matrix_a, 16, 16, 8, wmma::precision::tf32, wmma::row_major> af[2];
            #pragma unroll
            for (int i = 0; i < 2; i++) {
                wmma::load_matrix_sync(af[i], &As[cur][wr + i * 16][ks * 8], BKP);
                #pragma unroll
                for (int t = 0; t < af[i].num_elements; t++)
                    af[i].x[t] = wmma::__float_to_tf32(af[i].x[t]);
            }
            #pragma unroll
            for (int j = 0; j < 4; j++) {
                if (TB) {
                    wmma::fragment<wmma::matrix_b, 16, 16, 8, wmma::precision::tf32, wmma::col_major> bf;
                    wmma::load_matrix_sync(bf, &Bs[cur][wc + j * 16][ks * 8], BKP);
                    #pragma unroll
                    for (int t = 0; t < bf.num_elements; t++) bf.x[t] = wmma::__float_to_tf32(bf.x[t]);
                    wmma::mma_sync(acc[0][j], af[0], bf, acc[0][j]);
                    wmma::mma_sync(acc[1][j], af[1], bf, acc[1][j]);
                } else {
                    wmma::fragment<wmma::matrix_b, 16, 16, 8, wmma::precision::tf32, wmma::row_major> bf;
                    wmma::load_matrix_sync(bf, &Bs[cur][ks * 8][wc + j * 16], BNP);
                    #pragma unroll
                    for (int t = 0; t < bf.num_elements; t++) bf.x[t] = wmma::__float_to_tf32(bf.x[t]);
                    wmma::mma_sync(acc[0][j], af[0], bf, acc[0][j]);
                    wmma::mma_sync(acc[1][j], af[1], bf, acc[1][j]);
                }
            }
        }
        if (more) {
            int nxt = cur ^ 1;
            *(float4*)&As[nxt][ar][ac]      = pa0;
            *(float4*)&As[nxt][ar + 64][ac] = pa1;
            if (TB) { *(float4*)&Bs[nxt][br][bcd] = pb0; *(float4*)&Bs[nxt][br + 64][bcd] = pb1; }
            else    { *(float4*)&Bs[nxt][br][bcd] = pb0; *(float4*)&Bs[nxt][br + 8][bcd]  = pb1; }
        }
        __syncthreads();
    }

    #pragma unroll
    for (int i = 0; i < 2; i++)
        #pragma unroll
        for (int j = 0; j < 4; j++) {
            #pragma unroll
            for (int t = 0; t < acc[i][j].num_elements; t++) acc[i][j].x[t] *= p.alpha;
            float* cp = C + (long)(i0 + wr + i * 16) * p.ldc + j0 + wc + j * 16;
            if (p.beta) {
                wmma::fragment<wmma::accumulator, 16, 16, 8, float> cf;
                wmma::load_matrix_sync(cf, cp, p.ldc, wmma::mem_row_major);
                #pragma unroll
                for (int t = 0; t < acc[i][j].num_elements; t++) acc[i][j].x[t] += cf.x[t];
            }
            wmma::store_matrix_sync(cp, acc[i][j], p.ldc, wmma::mem_row_major);
        }
}

// ---------------- transpose (z, R x C) -> (z, C x R) ----------------
__global__ void transpose_k(const float* __restrict__ in, float* __restrict__ out, int R, int C) {
    __shared__ float t[32][33];
    long bo = (long)blockIdx.z * R * C;
    int r0 = blockIdx.y * 32, c0 = blockIdx.x * 32;
    int tx = threadIdx.x, ty = threadIdx.y;
    #pragma unroll
    for (int k = 0; k < 32; k += 8)
        t[ty + k][tx] = in[bo + (long)(r0 + ty + k) * C + c0 + tx];
    __syncthreads();
    #pragma unroll
    for (int k = 0; k < 32; k += 8)
        out[bo + (long)(c0 + ty + k) * R + r0 + tx] = t[tx][ty + k];
}

// ---------------- broadcast: per-(b,d) channel, in place on g_xt ----------------
__global__ void __launch_bounds__(256) bcast_k(float* xt) {
    __shared__ float a[SS];
    float res[32], nv[32];
    float* g = xt + (long)blockIdx.x * SS;
    int tid = threadIdx.x;
    #pragma unroll
    for (int j = 0; j < 32; j++) { a[tid + 256 * j] = g[tid + 256 * j]; res[j] = 0.0f; }
    __syncthreads();
    for (int s = 1; s < SS; s <<= 1) {
        #pragma unroll
        for (int j = 0; j < 32; j++) {
            int i = tid + 256 * j;
            nv[j] = a[i] + 0.5f * (a[(i - s) & (SS - 1)] + a[(i + s) & (SS - 1)]);
        }
        __syncthreads();
        #pragma unroll
        for (int j = 0; j < 32; j++) { int i = tid + 256 * j; a[i] = nv[j]; res[j] += nv[j]; }
        __syncthreads();
    }
    const float inv = 1.0f / 14.0f;
    #pragma unroll
    for (int j = 0; j < 32; j++) g[tid + 256 * j] = res[j] * inv;
}

// ---------------- Wc (o,d,k) -> Wc2 (o, k*1024+d) ----------------
__global__ void wc_reorder(const float* __restrict__ Wc, float* __restrict__ Wc2) {
    long idx = (long)blockIdx.x * 256 + threadIdx.x;
    int o = (int)(idx >> 12);
    int rem = (int)(idx & 4095);
    int k = rem >> 10;
    int d = rem & 1023;
    Wc2[idx] = Wc[(long)o * 4096 + d * 4 + k];
}

// ---------------- gt init: rows<128 = bc (bias preload), rows>=128 = gm ----------------
__global__ void build_gt(const float* __restrict__ gm, const float* __restrict__ bc, float* __restrict__ gt) {
    long idx = (long)blockIdx.x * 256 + threadIdx.x;
    int d = (int)(idx & 1023);
    int row = (int)((idx >> 10) & 255);
    gt[idx] = (row < GG) ? bc[d] : gm[(long)(row - GG) * DD + d];
}

__device__ __forceinline__ float blk_max(float v, float* red) {
    int tid = threadIdx.x;
    #pragma unroll
    for (int o = 16; o; o >>= 1) v = fmaxf(v, __shfl_xor_sync(0xffffffffu, v, o));
    if ((tid & 31) == 0) red[tid >> 5] = v;
    __syncthreads();
    float m = red[0];
    #pragma unroll
    for (int i = 1; i < 8; i++) m = fmaxf(m, red[i]);
    return m;
}
__device__ __forceinline__ float blk_sum(float v, float* red) {
    int tid = threadIdx.x;
    #pragma unroll
    for (int o = 16; o; o >>= 1) v += __shfl_xor_sync(0xffffffffu, v, o);
    if ((tid & 31) == 0) red[tid >> 5] = v;
    __syncthreads();
    float s = 0.f;
    #pragma unroll
    for (int i = 0; i < 8; i++) s += red[i];
    return s;
}

// ---------------- softmax over 256 keys ----------------
__global__ void softmax256(float* __restrict__ L) {
    __shared__ float red[8];
    float* r = L + (long)blockIdx.x * 256;
    int tid = threadIdx.x;
    float v = r[tid];
    float m = blk_max(v, red);
    __syncthreads();
    float e = expf(v - m);
    float s = blk_sum(e, red);
    r[tid] = e / s;
}

// ---------------- causal softmax, zero-fill to row-block edge ----------------
__global__ void softmax_causal(float* __restrict__ Sc) {
    __shared__ float red[8];
    int q = blockIdx.x, w = blockIdx.y;
    float* r = Sc + ((long)w * WLEN + q) * WLEN;
    int len = q + 1;
    int rb = ((q >> 7) + 1) << 7;
    int tid = threadIdx.x;
    float v[8];
    int cnt = 0;
    float m = -1e30f;
    for (int i = tid; i < len; i += 256) { v[cnt] = r[i]; m = fmaxf(m, v[cnt]); cnt++; }
    m = blk_max(m, red);
    __syncthreads();
    float s = 0.f;
    #pragma unroll
    for (int j = 0; j < 8; j++) if (j < cnt) { v[j] = expf(v[j] - m); s += v[j]; }
    s = blk_sum(s, red);
    float inv = 1.0f / s;
    cnt = 0;
    for (int i = tid; i < len; i += 256) r[i] = v[cnt++] * inv;
    for (int i = len + tid; i < rb; i += 256) r[i] = 0.0f;
}

// ---------------- gather window outputs -> local ----------------
__global__ void combine_local(const float* __restrict__ Oscr, float* __restrict__ local) {
    long idx = (long)blockIdx.x * 256 + threadIdx.x;
    int d = (int)(idx & 1023);
    long pd = idx >> 10;
    int p = (int)(pd & (SS - 1));
    int b = (int)(pd >> 13);
    int nhi = p >> 10;
    int n1 = min(nhi, NWIN - 1);
    int n0 = max(nhi - 1, 0);
    float acc = 0.f, wsum = 0.f;
    for (int n = n0; n <= n1; n++) {
        int q = p - (n << 10);
        float tri = 0.5f + q * (1.0f / 2047.0f);
        acc  += Oscr[(((long)(b * NWIN + n)) * WLEN + q) * DD + d] * tri;
        wsum += tri;
    }
    local[idx] = acc / (wsum + 1e-6f);
}

// ---------------- gate + mix ----------------
__global__ void sigmoid_mix(const float* __restrict__ mwl, const float* __restrict__ bm,
                            const float* __restrict__ local, const float* __restrict__ glob,
                            const float* __restrict__ bcast, float* __restrict__ mixed) {
    long idx = (long)blockIdx.x * 256 + threadIdx.x;
    int o = (int)(idx & 1023);
    float g = 1.0f / (1.0f + expf(-(mwl[idx] + bm[o])));
    mixed[idx] = g * local[idx] + (1.0f - g) * glob[idx] + bcast[idx];
}

__global__ void fill_bias(float* __restrict__ out, const float* __restrict__ bo) {
    long idx = (long)blockIdx.x * 256 + threadIdx.x;
    out[idx] = bo[idx & 1023];
}

extern "C" void kernel_launch(void* const* d_in, const int* in_sizes, int n_in,
                              void* d_out, int out_size) {
    const float* x  = (const float*)d_in[0];
    const float* gm = (const float*)d_in[1];
    const float* Wc = (const float*)d_in[2];
    const float* bc = (const float*)d_in[3];
    const float* Wm = (const float*)d_in[4];
    const float* bm = (const float*)d_in[5];
    const float* Wo = (const float*)d_in[6];
    const float* bo = (const float*)d_in[7];
    float* out = (float*)d_out;

    float *Sscr, *Oscr, *local, *glob, *xt, *bcast, *gt, *lg2, *Wc2;
    cudaGetSymbolAddress((void**)&Sscr,  g_Sscr);
    cudaGetSymbolAddress((void**)&Oscr,  g_Oscr);
    cudaGetSymbolAddress((void**)&local, g_local);
    cudaGetSymbolAddress((void**)&glob,  g_glob);
    cudaGetSymbolAddress((void**)&xt,    g_xt);
    cudaGetSymbolAddress((void**)&bcast, g_bcast);
    cudaGetSymbolAddress((void**)&gt,    g_gt);
    cudaGetSymbolAddress((void**)&lg2,   g_lg2);
    cudaGetSymbolAddress((void**)&Wc2,   g_Wc2);

    const float isq = 1.0f / 32.0f;   // 1/sqrt(1024)
    const long SD = (long)SS * DD;

    // 1) Wc reorder + gt build
    wc_reorder<<<16384, 256>>>(Wc, Wc2);
    build_gt<<<2048, 256>>>(gm, bc, gt);

    // 2) comp = x_view(128,4096) @ Wc2^T  (+bc preloaded), into gt rows 0..127
    {
        GP p{x, Wc2, gt, 4096, 4096, 1024, SD, 0, 256L * 1024, 4096, 1.0f, 1, 0, 0, 0, 0};
        gemm_tf32<1><<<dim3(8, 1, 2), 256>>>(p);
    }
    // 3) logits = x @ gt^T / 32
    {
        GP p{x, gt, lg2, 1024, 1024, 256, SD, 256L * 1024, (long)SS * 256, 1024, isq, 0, 0, 0, 0, 0};
        gemm_tf32<1><<<dim3(2, 64, 2), 256>>>(p);
    }
    softmax256<<<BB * SS, 256>>>(lg2);
    // 4) glob = attn @ gt
    {
        GP p{lg2, gt, glob, 256, 1024, 1024, (long)SS * 256, 256L * 1024, SD, 256, 1.0f, 0, 0, 0, 0, 0};
        gemm_tf32<0><<<dim3(8, 64, 2), 256>>>(p);
    }
    // 5) window scores = w @ w^T / 32 (causal tile-skip)
    {
        GP p{x, x, Sscr, 1024, 1024, WLEN, 0, 0, (long)WLEN * WLEN, 1024, isq, 0, 1, 1, 1, 0};
        gemm_tf32<1><<<dim3(16, 16, NBW), 256>>>(p);
    }
    softmax_causal<<<dim3(WLEN, NBW), 256>>>(Sscr);
    // 6) out_w = P @ w   (K limited per row block by causality)
    {
        GP p{Sscr, x, Oscr, WLEN, 1024, 1024, (long)WLEN * WLEN, 0, (long)WLEN * DD, WLEN, 1.0f, 0, 0, 1, 0, 1};
        gemm_tf32<0><<<dim3(8, 16, NBW), 256>>>(p);
    }
    combine_local<<<65536, 256>>>(Oscr, local);

    // 7) broadcast path
    transpose_k<<<dim3(32, 256, 2), dim3(32, 8)>>>(x, xt, SS, DD);
    bcast_k<<<BB * DD, 256>>>(xt);
    transpose_k<<<dim3(256, 32, 2), dim3(32, 8)>>>(xt, bcast, DD, SS);

    // 8) mw logits = local @ Wm[:, :D]^T + glob @ Wm[:, D:]^T  (into Sscr reuse)
    {
        GP p{local, Wm, Sscr, 1024, 2048, 1024, SD, 0, SD, 1024, 1.0f, 0, 0, 0, 0, 0};
        gemm_tf32<1><<<dim3(8, 64, 2), 256>>>(p);
    }
    {
        GP p{glob, Wm + 1024, Sscr, 1024, 2048, 1024, SD, 0, SD, 1024, 1.0f, 1, 0, 0, 0, 0};
        gemm_tf32<1><<<dim3(8, 64, 2), 256>>>(p);
    }
    sigmoid_mix<<<65536, 256>>>(Sscr, bm, local, glob, bcast, Oscr);

    // 9) out = mixed @ Wo^T + bo
    fill_bias<<<65536, 256>>>(out, bo);
    {
        GP p{Oscr, Wo, out, 1024, 1024, 1024, SD, 0, SD, 1024, 1.0f, 1, 0, 0, 0, 0};
        gemm_tf32<1><<<dim3(8, 64, 2), 256>>>(p);
    }
}